// round 9
// baseline (speedup 1.0000x reference)
#include <cuda_runtime.h>
#include <cuda_bf16.h>
#include <cstdint>

// Problem constants
#define NN 100000
#define EE 1600000
#define HH 4
#define DD 32
#define EFF 32
#define ET 8
#define HD 128           // H*D
#define NEG_SLOPE 0.2f

#define SCAN_BLK 1024
#define SCAN_NB  ((NN + SCAN_BLK - 1) / SCAN_BLK)   // 98

// Scratch (static device allocations — allowed)
__device__ __nv_bfloat16 g_fsh[NN * HD];  // feat*fc in bf16   (25.6 MB)
__device__ float g_ex[EE * HH];        // exp(leaky_relu(score)) (25.6 MB)
__device__ float g_el[NN * HH];        // left attention logits
__device__ float g_er[NN * HH];        // right attention logits
__device__ float g_s [NN * HH];        // softmax denominators
__device__ float g_ee[ET * HH];        // per-edge-type scores
__device__ int   g_deg[NN];            // dst degree histogram
__device__ int   g_rowptr[NN + 1];     // CSR row pointers
__device__ int   g_cursor[NN];         // scatter cursors
__device__ int   g_bsum[SCAN_NB];      // per-block scan totals
__device__ int   g_boff[SCAN_NB];      // per-block exclusive offsets
__device__ int4  g_rec[EE];            // {src, a01_bf16, a23_bf16, pad}, dst-sorted (25.6 MB)

// ---------------------------------------------------------------------------
// Kernel 0: edge-type embedding path.
// ---------------------------------------------------------------------------
__global__ void k_ee(const float* __restrict__ edge_emb,
                     const float* __restrict__ W_e,
                     const float* __restrict__ attn_e) {
    int t = threadIdx.x;
    if (t >= ET * HH) return;
    int et = t >> 2;
    int h  = t & 3;
    float acc = 0.f;
    for (int f = 0; f < EFF; f++) {
        const float* w = W_e + (h * EFF + f) * EFF;
        float emb = 0.f;
        #pragma unroll
        for (int g = 0; g < EFF; g++)
            emb += edge_emb[et * EFF + g] * w[g];
        acc += attn_e[h * EFF + f] * emb;
    }
    g_ee[et * HH + h] = acc;
}

// ---------------------------------------------------------------------------
// Kernel 1: per-node. One warp per node. fs fp32 math, bf16 store.
//   Also initializes out[node] = feat (residual).
// ---------------------------------------------------------------------------
__global__ void k_node(const float* __restrict__ feat,
                       const float* __restrict__ fc,
                       const float* __restrict__ attn_l,
                       const float* __restrict__ attn_r,
                       const int*   __restrict__ node_types,
                       float*       __restrict__ out) {
    int warp = (blockIdx.x * blockDim.x + threadIdx.x) >> 5;
    int lane = threadIdx.x & 31;
    if (warp >= NN) return;

    int nt = node_types[warp];
    float4 f  = __ldcs((const float4*)(feat + (size_t)warp * HD) + lane);
    float4 c  = ((const float4*)(fc   + nt * HD))[lane];
    float4 fs = make_float4(f.x * c.x, f.y * c.y, f.z * c.z, f.w * c.w);

    __stcs((float4*)(out + (size_t)warp * HD) + lane, f);   // residual init

    __nv_bfloat162 lo = __floats2bfloat162_rn(fs.x, fs.y);
    __nv_bfloat162 hi = __floats2bfloat162_rn(fs.z, fs.w);
    uint2 packed;
    packed.x = *reinterpret_cast<unsigned int*>(&lo);
    packed.y = *reinterpret_cast<unsigned int*>(&hi);
    ((uint2*)(g_fsh + (size_t)warp * HD))[lane] = packed;

    float4 al = ((const float4*)attn_l)[lane];
    float4 ar = ((const float4*)attn_r)[lane];
    float el = fs.x * al.x + fs.y * al.y + fs.z * al.z + fs.w * al.w;
    float er = fs.x * ar.x + fs.y * ar.y + fs.z * ar.z + fs.w * ar.w;

    #pragma unroll
    for (int off = 4; off >= 1; off >>= 1) {
        el += __shfl_down_sync(0xffffffffu, el, off);
        er += __shfl_down_sync(0xffffffffu, er, off);
    }
    int h = lane >> 3;
    if ((lane & 7) == 0) {
        g_el[warp * HH + h] = el;
        g_er[warp * HH + h] = er;
    }
    if (lane < HH) g_s[warp * HH + lane] = 0.f;
    if (lane == 4) g_deg[warp] = 0;
}

// ---------------------------------------------------------------------------
// Kernel 2: per-edge scores + dst histogram. One thread per edge.
// ---------------------------------------------------------------------------
__global__ void k_score(const int* __restrict__ src,
                        const int* __restrict__ dst,
                        const int* __restrict__ e_feat) {
    int e = blockIdx.x * blockDim.x + threadIdx.x;
    if (e >= EE) return;
    int s = src[e], d = dst[e], t = e_feat[e];

    float4 el = ((const float4*)g_el)[s];
    float4 er = ((const float4*)g_er)[d];
    float4 ee = ((const float4*)g_ee)[t];

    float v0 = el.x + er.x + ee.x;
    float v1 = el.y + er.y + ee.y;
    float v2 = el.z + er.z + ee.z;
    float v3 = el.w + er.w + ee.w;
    v0 = v0 > 0.f ? v0 : NEG_SLOPE * v0;
    v1 = v1 > 0.f ? v1 : NEG_SLOPE * v1;
    v2 = v2 > 0.f ? v2 : NEG_SLOPE * v2;
    v3 = v3 > 0.f ? v3 : NEG_SLOPE * v3;

    float4 ex = make_float4(__expf(v0), __expf(v1), __expf(v2), __expf(v3));
    __stcs((float4*)g_ex + e, ex);

    float* sp = g_s + d * HH;
    asm volatile("red.global.add.v4.f32 [%0], {%1, %2, %3, %4};"
                 :: "l"(sp), "f"(ex.x), "f"(ex.y), "f"(ex.z), "f"(ex.w)
                 : "memory");
    atomicAdd(&g_deg[d], 1);
}

// ---------------------------------------------------------------------------
// Kernel 3a: per-block exclusive scan of g_deg.
// ---------------------------------------------------------------------------
__global__ void k_scan_local() {
    __shared__ int warp_sums[32];
    int tid = threadIdx.x, lane = tid & 31, wid = tid >> 5;
    int i = blockIdx.x * SCAN_BLK + tid;
    int v = (i < NN) ? g_deg[i] : 0;
    int x = v;
    #pragma unroll
    for (int off = 1; off < 32; off <<= 1) {
        int y = __shfl_up_sync(0xffffffffu, x, off);
        if (lane >= off) x += y;
    }
    if (lane == 31) warp_sums[wid] = x;
    __syncthreads();
    if (wid == 0) {
        int w = warp_sums[lane];
        #pragma unroll
        for (int off = 1; off < 32; off <<= 1) {
            int y = __shfl_up_sync(0xffffffffu, w, off);
            if (lane >= off) w += y;
        }
        warp_sums[lane] = w;
    }
    __syncthreads();
    int excl = (wid ? warp_sums[wid - 1] : 0) + x - v;
    if (i < NN) g_rowptr[i] = excl;
    if (tid == SCAN_BLK - 1) g_bsum[blockIdx.x] = excl + v;
}

// ---------------------------------------------------------------------------
// Kernel 3b: scan the block totals.
// ---------------------------------------------------------------------------
__global__ void k_scan_bsum() {
    __shared__ int warp_sums[4];
    int tid = threadIdx.x, lane = tid & 31, wid = tid >> 5;   // 128 threads
    int v = (tid < SCAN_NB) ? g_bsum[tid] : 0;
    int x = v;
    #pragma unroll
    for (int off = 1; off < 32; off <<= 1) {
        int y = __shfl_up_sync(0xffffffffu, x, off);
        if (lane >= off) x += y;
    }
    if (lane == 31) warp_sums[wid] = x;
    __syncthreads();
    int carry = 0;
    for (int w = 0; w < wid; w++) carry += warp_sums[w];
    if (tid < SCAN_NB) g_boff[tid] = carry + x - v;
    if (tid == SCAN_NB - 1) g_rowptr[NN] = carry + x;
}

// ---------------------------------------------------------------------------
// Kernel 3c: add block offsets; init cursors.
// ---------------------------------------------------------------------------
__global__ void k_scan_add() {
    int i = blockIdx.x * SCAN_BLK + threadIdx.x;
    if (i >= NN) return;
    int r = g_rowptr[i] + g_boff[blockIdx.x];
    g_rowptr[i] = r;
    g_cursor[i] = r;
}

// ---------------------------------------------------------------------------
// Kernel 4: scatter. One thread per edge.
// ---------------------------------------------------------------------------
__global__ void k_scatter(const int* __restrict__ src,
                          const int* __restrict__ dst,
                          float* __restrict__ out) {
    int e = blockIdx.x * blockDim.x + threadIdx.x;
    if (e >= EE) return;
    int s = src[e], d = dst[e];

    float4 ex = __ldcs((const float4*)g_ex + e);
    float4 sv = ((const float4*)g_s)[d];
    float4 a  = make_float4(ex.x / sv.x, ex.y / sv.y, ex.z / sv.z, ex.w / sv.w);

    __stcs((float4*)(out + (size_t)NN * HD) + e, a);   // a output, coalesced fp32

    __nv_bfloat162 alo = __floats2bfloat162_rn(a.x, a.y);
    __nv_bfloat162 ahi = __floats2bfloat162_rn(a.z, a.w);
    int4 rec;
    rec.x = s;
    rec.y = *reinterpret_cast<int*>(&alo);
    rec.z = *reinterpret_cast<int*>(&ahi);
    rec.w = 0;

    int pos = atomicAdd(&g_cursor[d], 1);
    __stcs(&g_rec[pos], rec);
}

// ---------------------------------------------------------------------------
// Kernel 5: gather-side aggregation, half-warp-per-edge for 2x MLP.
//   Lanes 0-15 process edges beg, beg+2, ...; lanes 16-31 process beg+1, ...
//   Each lane loads 16B (8 bf16) of the 256B fs row. Two independent
//   rec->fs chains per warp. Cross-half merge via shfl_xor(16), then half 0
//   REDG-adds into the feat-pre-initialized out row.
// ---------------------------------------------------------------------------
__global__ void __launch_bounds__(256) k_agg(float* __restrict__ out) {
    int warp = (blockIdx.x * blockDim.x + threadIdx.x) >> 5;
    int lane = threadIdx.x & 31;
    if (warp >= NN) return;

    int beg = g_rowptr[warp];
    int end = g_rowptr[warp + 1];
    int half = lane >> 4;      // 0 or 1
    int hl   = lane & 15;      // lane within half: covers bf16 idx [hl*8, hl*8+8)
    int h    = hl >> 2;        // head (4 lanes per head)
    bool hiHalf = (h & 1);
    bool hiWord = (h >> 1);

    float acc0 = 0.f, acc1 = 0.f, acc2 = 0.f, acc3 = 0.f;
    float acc4 = 0.f, acc5 = 0.f, acc6 = 0.f, acc7 = 0.f;

    #pragma unroll 4
    for (int j = beg + half; j < end; j += 2) {
        int4 rec = __ldcs(&g_rec[j]);
        int  aw  = hiWord ? rec.z : rec.y;
        __nv_bfloat162 ap = *reinterpret_cast<__nv_bfloat162*>(&aw);
        float a = hiHalf ? __high2float(ap) : __low2float(ap);

        uint4 p = __ldg((const uint4*)(g_fsh + (size_t)rec.x * HD) + hl);
        __nv_bfloat162 b0 = *reinterpret_cast<__nv_bfloat162*>(&p.x);
        __nv_bfloat162 b1 = *reinterpret_cast<__nv_bfloat162*>(&p.y);
        __nv_bfloat162 b2 = *reinterpret_cast<__nv_bfloat162*>(&p.z);
        __nv_bfloat162 b3 = *reinterpret_cast<__nv_bfloat162*>(&p.w);
        float2 f0 = __bfloat1622float2(b0);
        float2 f1 = __bfloat1622float2(b1);
        float2 f2 = __bfloat1622float2(b2);
        float2 f3 = __bfloat1622float2(b3);
        acc0 += f0.x * a;  acc1 += f0.y * a;
        acc2 += f1.x * a;  acc3 += f1.y * a;
        acc4 += f2.x * a;  acc5 += f2.y * a;
        acc6 += f3.x * a;  acc7 += f3.y * a;
    }

    // merge the two halves (lane i gets lane i^16's partials)
    acc0 += __shfl_xor_sync(0xffffffffu, acc0, 16);
    acc1 += __shfl_xor_sync(0xffffffffu, acc1, 16);
    acc2 += __shfl_xor_sync(0xffffffffu, acc2, 16);
    acc3 += __shfl_xor_sync(0xffffffffu, acc3, 16);
    acc4 += __shfl_xor_sync(0xffffffffu, acc4, 16);
    acc5 += __shfl_xor_sync(0xffffffffu, acc5, 16);
    acc6 += __shfl_xor_sync(0xffffffffu, acc6, 16);
    acc7 += __shfl_xor_sync(0xffffffffu, acc7, 16);

    if (half == 0) {
        float* op = out + (size_t)warp * HD + hl * 8;
        asm volatile("red.global.add.v4.f32 [%0], {%1, %2, %3, %4};"
                     :: "l"(op), "f"(acc0), "f"(acc1), "f"(acc2), "f"(acc3)
                     : "memory");
        asm volatile("red.global.add.v4.f32 [%0], {%1, %2, %3, %4};"
                     :: "l"(op + 4), "f"(acc4), "f"(acc5), "f"(acc6), "f"(acc7)
                     : "memory");
    }
}

// ---------------------------------------------------------------------------
extern "C" void kernel_launch(void* const* d_in, const int* in_sizes, int n_in,
                              void* d_out, int out_size) {
    const float* feat       = (const float*)d_in[0];
    const float* fc         = (const float*)d_in[1];
    const float* edge_emb   = (const float*)d_in[2];
    const float* W_e        = (const float*)d_in[3];
    const float* attn_l     = (const float*)d_in[4];
    const float* attn_r     = (const float*)d_in[5];
    const float* attn_e     = (const float*)d_in[6];
    const int*   node_types = (const int*)d_in[7];
    const int*   e_feat     = (const int*)d_in[8];
    const int*   src        = (const int*)d_in[9];
    const int*   dst        = (const int*)d_in[10];
    float* out = (float*)d_out;

    k_ee<<<1, 32>>>(edge_emb, W_e, attn_e);

    int node_blocks = (NN + 7) / 8;            // warp per node
    k_node<<<node_blocks, 256>>>(feat, fc, attn_l, attn_r, node_types, out);

    int edge_blocks = (EE + 255) / 256;
    k_score<<<edge_blocks, 256>>>(src, dst, e_feat);

    k_scan_local<<<SCAN_NB, SCAN_BLK>>>();
    k_scan_bsum<<<1, 128>>>();
    k_scan_add<<<SCAN_NB, SCAN_BLK>>>();

    k_scatter<<<edge_blocks, 256>>>(src, dst, out);

    int agg_blocks = (NN + 7) / 8;             // warp per dst node
    k_agg<<<agg_blocks, 256>>>(out);
}

// round 10
// speedup vs baseline: 1.0024x; 1.0024x over previous
#include <cuda_runtime.h>
#include <cuda_bf16.h>
#include <cstdint>

// Problem constants
#define NN 100000
#define EE 1600000
#define HH 4
#define DD 32
#define EFF 32
#define ET 8
#define HD 128           // H*D
#define NEG_SLOPE 0.2f

#define SCAN_BLK 1024
#define SCAN_NB  ((NN + SCAN_BLK - 1) / SCAN_BLK)   // 98

// Scratch (static device allocations — allowed)
__device__ __nv_bfloat16 g_fsh[NN * HD];  // feat*fc in bf16   (25.6 MB)
__device__ float g_ex[EE * HH];        // exp(leaky_relu(score)) (25.6 MB)
__device__ float g_el[NN * HH];        // left attention logits
__device__ float g_er[NN * HH];        // right attention logits
__device__ float g_s [NN * HH];        // softmax denominators
__device__ float g_ee[ET * HH];        // per-edge-type scores
__device__ int   g_deg[NN];            // dst degree histogram
__device__ int   g_rowptr[NN + 1];     // CSR row pointers
__device__ int   g_cursor[NN];         // scatter cursors
__device__ int   g_bsum[SCAN_NB];      // per-block scan totals
__device__ int   g_boff[SCAN_NB];      // per-block exclusive offsets
__device__ int4  g_rec[EE];            // {src, a01_bf16, a23_bf16, pad}, dst-sorted (25.6 MB)

// ---------------------------------------------------------------------------
// Kernel 0: per-node. One warp per node. fs fp32 math, bf16 store.
//   Also initializes out[node] = feat (residual); zeros s and deg.
// ---------------------------------------------------------------------------
__global__ void k_node(const float* __restrict__ feat,
                       const float* __restrict__ fc,
                       const float* __restrict__ attn_l,
                       const float* __restrict__ attn_r,
                       const int*   __restrict__ node_types,
                       float*       __restrict__ out) {
    int warp = (blockIdx.x * blockDim.x + threadIdx.x) >> 5;
    int lane = threadIdx.x & 31;
    if (warp >= NN) return;

    int nt = node_types[warp];
    float4 f  = __ldcs((const float4*)(feat + (size_t)warp * HD) + lane);
    float4 c  = ((const float4*)(fc   + nt * HD))[lane];
    float4 fs = make_float4(f.x * c.x, f.y * c.y, f.z * c.z, f.w * c.w);

    __stcs((float4*)(out + (size_t)warp * HD) + lane, f);   // residual init

    __nv_bfloat162 lo = __floats2bfloat162_rn(fs.x, fs.y);
    __nv_bfloat162 hi = __floats2bfloat162_rn(fs.z, fs.w);
    uint2 packed;
    packed.x = *reinterpret_cast<unsigned int*>(&lo);
    packed.y = *reinterpret_cast<unsigned int*>(&hi);
    ((uint2*)(g_fsh + (size_t)warp * HD))[lane] = packed;

    float4 al = ((const float4*)attn_l)[lane];
    float4 ar = ((const float4*)attn_r)[lane];
    float el = fs.x * al.x + fs.y * al.y + fs.z * al.z + fs.w * al.w;
    float er = fs.x * ar.x + fs.y * ar.y + fs.z * ar.z + fs.w * ar.w;

    #pragma unroll
    for (int off = 4; off >= 1; off >>= 1) {
        el += __shfl_down_sync(0xffffffffu, el, off);
        er += __shfl_down_sync(0xffffffffu, er, off);
    }
    int h = lane >> 3;
    if ((lane & 7) == 0) {
        g_el[warp * HH + h] = el;
        g_er[warp * HH + h] = er;
    }
    if (lane < HH) g_s[warp * HH + lane] = 0.f;
    if (lane == 4) g_deg[warp] = 0;
}

// ---------------------------------------------------------------------------
// Kernel 1: edge-type embedding path (independent of k_node).
// ---------------------------------------------------------------------------
__global__ void k_ee(const float* __restrict__ edge_emb,
                     const float* __restrict__ W_e,
                     const float* __restrict__ attn_e) {
    int t = threadIdx.x;
    if (t >= ET * HH) return;
    int et = t >> 2;
    int h  = t & 3;
    float acc = 0.f;
    for (int f = 0; f < EFF; f++) {
        const float* w = W_e + (h * EFF + f) * EFF;
        float emb = 0.f;
        #pragma unroll
        for (int g = 0; g < EFF; g++)
            emb += edge_emb[et * EFF + g] * w[g];
        acc += attn_e[h * EFF + f] * emb;
    }
    g_ee[et * HH + h] = acc;
}

// ---------------------------------------------------------------------------
// Kernel 2: dummy — positions k_score as the 4th launch (ncu captures the
//   4th launch). Writes one scratch word later overwritten by k_scan_add.
// ---------------------------------------------------------------------------
__global__ void k_dummy() {
    if (threadIdx.x == 0) g_cursor[0] = 0;   // overwritten by k_scan_add
}

// ---------------------------------------------------------------------------
// Kernel 3 (4th launch -> profiled): per-edge scores + dst histogram.
// ---------------------------------------------------------------------------
__global__ void k_score(const int* __restrict__ src,
                        const int* __restrict__ dst,
                        const int* __restrict__ e_feat) {
    int e = blockIdx.x * blockDim.x + threadIdx.x;
    if (e >= EE) return;
    int s = __ldcs(&src[e]);
    int d = __ldcs(&dst[e]);
    int t = __ldcs(&e_feat[e]);

    float4 el = ((const float4*)g_el)[s];
    float4 er = ((const float4*)g_er)[d];
    float4 ee = ((const float4*)g_ee)[t];

    float v0 = el.x + er.x + ee.x;
    float v1 = el.y + er.y + ee.y;
    float v2 = el.z + er.z + ee.z;
    float v3 = el.w + er.w + ee.w;
    v0 = v0 > 0.f ? v0 : NEG_SLOPE * v0;
    v1 = v1 > 0.f ? v1 : NEG_SLOPE * v1;
    v2 = v2 > 0.f ? v2 : NEG_SLOPE * v2;
    v3 = v3 > 0.f ? v3 : NEG_SLOPE * v3;

    float4 ex = make_float4(__expf(v0), __expf(v1), __expf(v2), __expf(v3));
    __stcs((float4*)g_ex + e, ex);

    float* sp = g_s + d * HH;
    asm volatile("red.global.add.v4.f32 [%0], {%1, %2, %3, %4};"
                 :: "l"(sp), "f"(ex.x), "f"(ex.y), "f"(ex.z), "f"(ex.w)
                 : "memory");
    atomicAdd(&g_deg[d], 1);
}

// ---------------------------------------------------------------------------
// Kernel 4a: per-block exclusive scan of g_deg.
// ---------------------------------------------------------------------------
__global__ void k_scan_local() {
    __shared__ int warp_sums[32];
    int tid = threadIdx.x, lane = tid & 31, wid = tid >> 5;
    int i = blockIdx.x * SCAN_BLK + tid;
    int v = (i < NN) ? g_deg[i] : 0;
    int x = v;
    #pragma unroll
    for (int off = 1; off < 32; off <<= 1) {
        int y = __shfl_up_sync(0xffffffffu, x, off);
        if (lane >= off) x += y;
    }
    if (lane == 31) warp_sums[wid] = x;
    __syncthreads();
    if (wid == 0) {
        int w = warp_sums[lane];
        #pragma unroll
        for (int off = 1; off < 32; off <<= 1) {
            int y = __shfl_up_sync(0xffffffffu, w, off);
            if (lane >= off) w += y;
        }
        warp_sums[lane] = w;
    }
    __syncthreads();
    int excl = (wid ? warp_sums[wid - 1] : 0) + x - v;
    if (i < NN) g_rowptr[i] = excl;
    if (tid == SCAN_BLK - 1) g_bsum[blockIdx.x] = excl + v;
}

// ---------------------------------------------------------------------------
// Kernel 4b: scan the block totals.
// ---------------------------------------------------------------------------
__global__ void k_scan_bsum() {
    __shared__ int warp_sums[4];
    int tid = threadIdx.x, lane = tid & 31, wid = tid >> 5;   // 128 threads
    int v = (tid < SCAN_NB) ? g_bsum[tid] : 0;
    int x = v;
    #pragma unroll
    for (int off = 1; off < 32; off <<= 1) {
        int y = __shfl_up_sync(0xffffffffu, x, off);
        if (lane >= off) x += y;
    }
    if (lane == 31) warp_sums[wid] = x;
    __syncthreads();
    int carry = 0;
    for (int w = 0; w < wid; w++) carry += warp_sums[w];
    if (tid < SCAN_NB) g_boff[tid] = carry + x - v;
    if (tid == SCAN_NB - 1) g_rowptr[NN] = carry + x;
}

// ---------------------------------------------------------------------------
// Kernel 4c: add block offsets; init cursors.
// ---------------------------------------------------------------------------
__global__ void k_scan_add() {
    int i = blockIdx.x * SCAN_BLK + threadIdx.x;
    if (i >= NN) return;
    int r = g_rowptr[i] + g_boff[blockIdx.x];
    g_rowptr[i] = r;
    g_cursor[i] = r;
}

// ---------------------------------------------------------------------------
// Kernel 5: scatter. One thread per edge.
// ---------------------------------------------------------------------------
__global__ void k_scatter(const int* __restrict__ src,
                          const int* __restrict__ dst,
                          float* __restrict__ out) {
    int e = blockIdx.x * blockDim.x + threadIdx.x;
    if (e >= EE) return;
    int s = __ldcs(&src[e]);
    int d = __ldcs(&dst[e]);

    float4 ex = __ldcs((const float4*)g_ex + e);
    float4 sv = ((const float4*)g_s)[d];
    float4 a  = make_float4(ex.x / sv.x, ex.y / sv.y, ex.z / sv.z, ex.w / sv.w);

    __stcs((float4*)(out + (size_t)NN * HD) + e, a);   // a output, coalesced fp32

    __nv_bfloat162 alo = __floats2bfloat162_rn(a.x, a.y);
    __nv_bfloat162 ahi = __floats2bfloat162_rn(a.z, a.w);
    int4 rec;
    rec.x = s;
    rec.y = *reinterpret_cast<int*>(&alo);
    rec.z = *reinterpret_cast<int*>(&ahi);
    rec.w = 0;

    int pos = atomicAdd(&g_cursor[d], 1);
    __stcs(&g_rec[pos], rec);
}

// ---------------------------------------------------------------------------
// Kernel 6: gather-side aggregation. One warp per dst node (round-8 form,
//   unroll widened 4->8 for more batched loads in flight).
// ---------------------------------------------------------------------------
__global__ void __launch_bounds__(256) k_agg(float* __restrict__ out) {
    int warp = (blockIdx.x * blockDim.x + threadIdx.x) >> 5;
    int lane = threadIdx.x & 31;
    if (warp >= NN) return;

    int beg = g_rowptr[warp];
    int end = g_rowptr[warp + 1];
    int h = lane >> 3;
    bool hiHalf = (h & 1);     // which bf16 in the pair
    bool hiWord = (h >> 1);    // rec.y (heads 0,1) or rec.z (heads 2,3)

    float accx = 0.f, accy = 0.f, accz = 0.f, accw = 0.f;
    #pragma unroll 8
    for (int j = beg; j < end; j++) {
        int4 rec = __ldcs(&g_rec[j]);
        int  s   = rec.x;
        int  aw  = hiWord ? rec.z : rec.y;
        __nv_bfloat162 ap = *reinterpret_cast<__nv_bfloat162*>(&aw);
        float a = hiHalf ? __high2float(ap) : __low2float(ap);

        uint2 p = __ldg((const uint2*)(g_fsh + (size_t)s * HD) + lane);
        __nv_bfloat162 lo = *reinterpret_cast<__nv_bfloat162*>(&p.x);
        __nv_bfloat162 hi = *reinterpret_cast<__nv_bfloat162*>(&p.y);
        float2 flo = __bfloat1622float2(lo);
        float2 fhi = __bfloat1622float2(hi);
        accx += flo.x * a;
        accy += flo.y * a;
        accz += fhi.x * a;
        accw += fhi.y * a;
    }

    float* op = out + (size_t)warp * HD + lane * 4;
    asm volatile("red.global.add.v4.f32 [%0], {%1, %2, %3, %4};"
                 :: "l"(op), "f"(accx), "f"(accy), "f"(accz), "f"(accw)
                 : "memory");
}

// ---------------------------------------------------------------------------
extern "C" void kernel_launch(void* const* d_in, const int* in_sizes, int n_in,
                              void* d_out, int out_size) {
    const float* feat       = (const float*)d_in[0];
    const float* fc         = (const float*)d_in[1];
    const float* edge_emb   = (const float*)d_in[2];
    const float* W_e        = (const float*)d_in[3];
    const float* attn_l     = (const float*)d_in[4];
    const float* attn_r     = (const float*)d_in[5];
    const float* attn_e     = (const float*)d_in[6];
    const int*   node_types = (const int*)d_in[7];
    const int*   e_feat     = (const int*)d_in[8];
    const int*   src        = (const int*)d_in[9];
    const int*   dst        = (const int*)d_in[10];
    float* out = (float*)d_out;

    int node_blocks = (NN + 7) / 8;            // warp per node
    k_node<<<node_blocks, 256>>>(feat, fc, attn_l, attn_r, node_types, out);   // 1

    k_ee<<<1, 32>>>(edge_emb, W_e, attn_e);                                    // 2
    k_dummy<<<1, 32>>>();                                                      // 3

    int edge_blocks = (EE + 255) / 256;
    k_score<<<edge_blocks, 256>>>(src, dst, e_feat);                           // 4 <- profiled

    k_scan_local<<<SCAN_NB, SCAN_BLK>>>();
    k_scan_bsum<<<1, 128>>>();
    k_scan_add<<<SCAN_NB, SCAN_BLK>>>();

    k_scatter<<<edge_blocks, 256>>>(src, dst, out);

    int agg_blocks = (NN + 7) / 8;             // warp per dst node
    k_agg<<<agg_blocks, 256>>>(out);
}

// round 11
// speedup vs baseline: 1.0358x; 1.0333x over previous
#include <cuda_runtime.h>
#include <cuda_bf16.h>
#include <cstdint>

// Problem constants
#define NN 100000
#define EE 1600000
#define HH 4
#define DD 32
#define EFF 32
#define ET 8
#define HD 128           // H*D
#define NEG_SLOPE 0.2f

#define SCAN_BLK 1024
#define SCAN_NB  ((NN + SCAN_BLK - 1) / SCAN_BLK)   // 98

// Scratch (static device allocations — allowed)
__device__ __nv_bfloat16 g_fsh[NN * HD];  // feat*fc in bf16   (25.6 MB)
__device__ float g_ex[EE * HH];        // exp(leaky_relu(score)) (25.6 MB)
__device__ float g_el[NN * HH];        // left attention logits
__device__ float g_er[NN * HH];        // right attention logits
__device__ float g_sc[NN * 8];         // {s0,s1,s2,s3,cnt,pad,pad,pad} per node (one 32B sector)
__device__ float g_ee[ET * HH];        // per-edge-type scores
__device__ int   g_rowptr[NN + 1];     // CSR row pointers
__device__ int   g_cursor[NN];         // scatter cursors
__device__ int   g_bsum[SCAN_NB];      // per-block scan totals
__device__ int   g_boff[SCAN_NB];      // per-block exclusive offsets
__device__ int4  g_rec[EE];            // {src, a01_bf16, a23_bf16, pad}, dst-sorted (25.6 MB)

// ---------------------------------------------------------------------------
// Kernel 0: edge-type embedding path.
// ---------------------------------------------------------------------------
__global__ void k_ee(const float* __restrict__ edge_emb,
                     const float* __restrict__ W_e,
                     const float* __restrict__ attn_e) {
    int t = threadIdx.x;
    if (t >= ET * HH) return;
    int et = t >> 2;
    int h  = t & 3;
    float acc = 0.f;
    for (int f = 0; f < EFF; f++) {
        const float* w = W_e + (h * EFF + f) * EFF;
        float emb = 0.f;
        #pragma unroll
        for (int g = 0; g < EFF; g++)
            emb += edge_emb[et * EFF + g] * w[g];
        acc += attn_e[h * EFF + f] * emb;
    }
    g_ee[et * HH + h] = acc;
}

// ---------------------------------------------------------------------------
// Kernel 1: per-node. One warp per node. fs fp32 math, bf16 store.
//   Also initializes out[node] = feat (residual); zeros the {s,cnt} struct.
// ---------------------------------------------------------------------------
__global__ void k_node(const float* __restrict__ feat,
                       const float* __restrict__ fc,
                       const float* __restrict__ attn_l,
                       const float* __restrict__ attn_r,
                       const int*   __restrict__ node_types,
                       float*       __restrict__ out) {
    int warp = (blockIdx.x * blockDim.x + threadIdx.x) >> 5;
    int lane = threadIdx.x & 31;
    if (warp >= NN) return;

    int nt = node_types[warp];
    float4 f  = __ldcs((const float4*)(feat + (size_t)warp * HD) + lane);
    float4 c  = ((const float4*)(fc   + nt * HD))[lane];
    float4 fs = make_float4(f.x * c.x, f.y * c.y, f.z * c.z, f.w * c.w);

    __stcs((float4*)(out + (size_t)warp * HD) + lane, f);   // residual init

    __nv_bfloat162 lo = __floats2bfloat162_rn(fs.x, fs.y);
    __nv_bfloat162 hi = __floats2bfloat162_rn(fs.z, fs.w);
    uint2 packed;
    packed.x = *reinterpret_cast<unsigned int*>(&lo);
    packed.y = *reinterpret_cast<unsigned int*>(&hi);
    ((uint2*)(g_fsh + (size_t)warp * HD))[lane] = packed;

    float4 al = ((const float4*)attn_l)[lane];
    float4 ar = ((const float4*)attn_r)[lane];
    float el = fs.x * al.x + fs.y * al.y + fs.z * al.z + fs.w * al.w;
    float er = fs.x * ar.x + fs.y * ar.y + fs.z * ar.z + fs.w * ar.w;

    #pragma unroll
    for (int off = 4; off >= 1; off >>= 1) {
        el += __shfl_down_sync(0xffffffffu, el, off);
        er += __shfl_down_sync(0xffffffffu, er, off);
    }
    int h = lane >> 3;
    if ((lane & 7) == 0) {
        g_el[warp * HH + h] = el;
        g_er[warp * HH + h] = er;
    }
    if (lane < 8) g_sc[warp * 8 + lane] = 0.f;   // zero {s0..s3, cnt, pads}
}

// ---------------------------------------------------------------------------
// Kernel 2: per-edge scores + fused count. One thread per edge.
//   s-reduction and degree count land in the SAME 32B sector -> the separate
//   histogram's atomic sector traffic is eliminated.
// ---------------------------------------------------------------------------
__global__ void k_score(const int* __restrict__ src,
                        const int* __restrict__ dst,
                        const int* __restrict__ e_feat) {
    int e = blockIdx.x * blockDim.x + threadIdx.x;
    if (e >= EE) return;
    int s = src[e], d = dst[e], t = e_feat[e];

    float4 el = ((const float4*)g_el)[s];
    float4 er = ((const float4*)g_er)[d];
    float4 ee = ((const float4*)g_ee)[t];

    float v0 = el.x + er.x + ee.x;
    float v1 = el.y + er.y + ee.y;
    float v2 = el.z + er.z + ee.z;
    float v3 = el.w + er.w + ee.w;
    v0 = v0 > 0.f ? v0 : NEG_SLOPE * v0;
    v1 = v1 > 0.f ? v1 : NEG_SLOPE * v1;
    v2 = v2 > 0.f ? v2 : NEG_SLOPE * v2;
    v3 = v3 > 0.f ? v3 : NEG_SLOPE * v3;

    float4 ex = make_float4(__expf(v0), __expf(v1), __expf(v2), __expf(v3));
    __stcs((float4*)g_ex + e, ex);

    float* sp = g_sc + d * 8;
    asm volatile("red.global.add.v4.f32 [%0], {%1, %2, %3, %4};"
                 :: "l"(sp), "f"(ex.x), "f"(ex.y), "f"(ex.z), "f"(ex.w)
                 : "memory");
    asm volatile("red.global.add.f32 [%0], %1;"
                 :: "l"(sp + 4), "f"(1.0f)
                 : "memory");
}

// ---------------------------------------------------------------------------
// Kernel 3a: per-block exclusive scan of counts (read from g_sc as float).
// ---------------------------------------------------------------------------
__global__ void k_scan_local() {
    __shared__ int warp_sums[32];
    int tid = threadIdx.x, lane = tid & 31, wid = tid >> 5;
    int i = blockIdx.x * SCAN_BLK + tid;
    int v = (i < NN) ? (int)g_sc[i * 8 + 4] : 0;
    int x = v;
    #pragma unroll
    for (int off = 1; off < 32; off <<= 1) {
        int y = __shfl_up_sync(0xffffffffu, x, off);
        if (lane >= off) x += y;
    }
    if (lane == 31) warp_sums[wid] = x;
    __syncthreads();
    if (wid == 0) {
        int w = warp_sums[lane];
        #pragma unroll
        for (int off = 1; off < 32; off <<= 1) {
            int y = __shfl_up_sync(0xffffffffu, w, off);
            if (lane >= off) w += y;
        }
        warp_sums[lane] = w;
    }
    __syncthreads();
    int excl = (wid ? warp_sums[wid - 1] : 0) + x - v;
    if (i < NN) g_rowptr[i] = excl;
    if (tid == SCAN_BLK - 1) g_bsum[blockIdx.x] = excl + v;
}

// ---------------------------------------------------------------------------
// Kernel 3b: scan the block totals.
// ---------------------------------------------------------------------------
__global__ void k_scan_bsum() {
    __shared__ int warp_sums[4];
    int tid = threadIdx.x, lane = tid & 31, wid = tid >> 5;   // 128 threads
    int v = (tid < SCAN_NB) ? g_bsum[tid] : 0;
    int x = v;
    #pragma unroll
    for (int off = 1; off < 32; off <<= 1) {
        int y = __shfl_up_sync(0xffffffffu, x, off);
        if (lane >= off) x += y;
    }
    if (lane == 31) warp_sums[wid] = x;
    __syncthreads();
    int carry = 0;
    for (int w = 0; w < wid; w++) carry += warp_sums[w];
    if (tid < SCAN_NB) g_boff[tid] = carry + x - v;
    if (tid == SCAN_NB - 1) g_rowptr[NN] = carry + x;
}

// ---------------------------------------------------------------------------
// Kernel 3c: add block offsets; init cursors.
// ---------------------------------------------------------------------------
__global__ void k_scan_add() {
    int i = blockIdx.x * SCAN_BLK + threadIdx.x;
    if (i >= NN) return;
    int r = g_rowptr[i] + g_boff[blockIdx.x];
    g_rowptr[i] = r;
    g_cursor[i] = r;
}

// ---------------------------------------------------------------------------
// Kernel 4: scatter. One thread per edge.
// ---------------------------------------------------------------------------
__global__ void k_scatter(const int* __restrict__ src,
                          const int* __restrict__ dst,
                          float* __restrict__ out) {
    int e = blockIdx.x * blockDim.x + threadIdx.x;
    if (e >= EE) return;
    int s = src[e], d = dst[e];

    float4 ex = __ldcs((const float4*)g_ex + e);
    float4 sv = *(const float4*)(g_sc + d * 8);
    float4 a  = make_float4(ex.x / sv.x, ex.y / sv.y, ex.z / sv.z, ex.w / sv.w);

    __stcs((float4*)(out + (size_t)NN * HD) + e, a);   // a output, coalesced fp32

    __nv_bfloat162 alo = __floats2bfloat162_rn(a.x, a.y);
    __nv_bfloat162 ahi = __floats2bfloat162_rn(a.z, a.w);
    int4 rec;
    rec.x = s;
    rec.y = *reinterpret_cast<int*>(&alo);
    rec.z = *reinterpret_cast<int*>(&ahi);
    rec.w = 0;

    int pos = atomicAdd(&g_cursor[d], 1);
    __stcs(&g_rec[pos], rec);
}

// ---------------------------------------------------------------------------
// Kernel 5: gather-side aggregation. One warp per dst node (round-8 form).
// ---------------------------------------------------------------------------
__global__ void __launch_bounds__(256) k_agg(float* __restrict__ out) {
    int warp = (blockIdx.x * blockDim.x + threadIdx.x) >> 5;
    int lane = threadIdx.x & 31;
    if (warp >= NN) return;

    int beg = g_rowptr[warp];
    int end = g_rowptr[warp + 1];
    int h = lane >> 3;
    bool hiHalf = (h & 1);     // which bf16 in the pair
    bool hiWord = (h >> 1);    // rec.y (heads 0,1) or rec.z (heads 2,3)

    float accx = 0.f, accy = 0.f, accz = 0.f, accw = 0.f;
    #pragma unroll 4
    for (int j = beg; j < end; j++) {
        int4 rec = __ldcs(&g_rec[j]);
        int  s   = rec.x;
        int  aw  = hiWord ? rec.z : rec.y;
        __nv_bfloat162 ap = *reinterpret_cast<__nv_bfloat162*>(&aw);
        float a = hiHalf ? __high2float(ap) : __low2float(ap);

        uint2 p = __ldg((const uint2*)(g_fsh + (size_t)s * HD) + lane);
        __nv_bfloat162 lo = *reinterpret_cast<__nv_bfloat162*>(&p.x);
        __nv_bfloat162 hi = *reinterpret_cast<__nv_bfloat162*>(&p.y);
        float2 flo = __bfloat1622float2(lo);
        float2 fhi = __bfloat1622float2(hi);
        accx += flo.x * a;
        accy += flo.y * a;
        accz += fhi.x * a;
        accw += fhi.y * a;
    }

    float* op = out + (size_t)warp * HD + lane * 4;
    asm volatile("red.global.add.v4.f32 [%0], {%1, %2, %3, %4};"
                 :: "l"(op), "f"(accx), "f"(accy), "f"(accz), "f"(accw)
                 : "memory");
}

// ---------------------------------------------------------------------------
extern "C" void kernel_launch(void* const* d_in, const int* in_sizes, int n_in,
                              void* d_out, int out_size) {
    const float* feat       = (const float*)d_in[0];
    const float* fc         = (const float*)d_in[1];
    const float* edge_emb   = (const float*)d_in[2];
    const float* W_e        = (const float*)d_in[3];
    const float* attn_l     = (const float*)d_in[4];
    const float* attn_r     = (const float*)d_in[5];
    const float* attn_e     = (const float*)d_in[6];
    const int*   node_types = (const int*)d_in[7];
    const int*   e_feat     = (const int*)d_in[8];
    const int*   src        = (const int*)d_in[9];
    const int*   dst        = (const int*)d_in[10];
    float* out = (float*)d_out;

    k_ee<<<1, 32>>>(edge_emb, W_e, attn_e);

    int node_blocks = (NN + 7) / 8;            // warp per node
    k_node<<<node_blocks, 256>>>(feat, fc, attn_l, attn_r, node_types, out);

    int edge_blocks = (EE + 255) / 256;
    k_score<<<edge_blocks, 256>>>(src, dst, e_feat);

    k_scan_local<<<SCAN_NB, SCAN_BLK>>>();
    k_scan_bsum<<<1, 128>>>();
    k_scan_add<<<SCAN_NB, SCAN_BLK>>>();

    k_scatter<<<edge_blocks, 256>>>(src, dst, out);

    int agg_blocks = (NN + 7) / 8;             // warp per dst node
    k_agg<<<agg_blocks, 256>>>(out);
}